// round 17
// baseline (speedup 1.0000x reference)
#include <cuda_runtime.h>
#include <cuda_bf16.h>

// Problem constants (match setup_inputs: P=1024, M=64, R=64)
#define P 1024
#define MDIM 64
#define RDIM 64
#define NTHR 256
#define PF 2       // software-pipeline depth (float4 buffers in flight)
#define QJ  256    // j's per stream block (quarter row)
#define NPRE    (P / 8)   // 128 precompute blocks at the FRONT of the grid
#define NSTREAM (P * 4)   // 4096 stream blocks

// Allocation-free scratch (__device__ globals; zero-init at load, self-resetting)
__device__ float g_hi[P];
__device__ float g_hj[P];
__device__ float g_dots[P * P];   // 4 MB: RAW dots only (attn never hits gmem)
__device__ int   g_rowcnt[P];     // quarters-done per row (reset by its finisher)
__device__ int   g_pre;           // precompute-ready counter
__device__ int   g_fin;           // finished rows (last one resets g_pre)

// ---------------------------------------------------------------------------
// ONE kernel, two roles:
//   blocks [0, 128):    precompute hi/hj (warp-per-row). Wave-1, never waits.
//   blocks [128, 4224): (row i, quarter q) stream 64 KB of rela via __ldcs,
//                       write raw dots. The row's 4th-quarter block (the
//                       "finisher") computes the full softmax IN REGISTERS,
//                       stages attn in SMEM, and performs the row GEMV
//                       out[i,:] = attn . hidden itself — all hidden under
//                       the DRAM stream of the other blocks. No second
//                       kernel, no atomics, no attn round-trip to DRAM.
// ---------------------------------------------------------------------------
__global__ __launch_bounds__(NTHR, 8) void fused_kernel(
    const float* __restrict__ rela,
    const float* __restrict__ hidden,
    const int*   __restrict__ nei,
    const float* __restrict__ W,
    const float* __restrict__ bptr,
    float* __restrict__ out)
{
    // stream role:   part  = pool[0..1279]  (QJ*5 padded partials)
    // finisher role: sat   = pool[0..1023]  (attn row)
    //                partb = pool[1024..1535] ([8][64] GEMV partials)
    __shared__ float pool[1536];
    __shared__ float red[8];
    __shared__ int   s_old;

    const int tid  = threadIdx.x;
    const int warp = tid >> 5;
    const int lane = tid & 31;

    // ================= role 1: precompute hi/hj =================
    if (blockIdx.x < NPRE) {
        const int row = blockIdx.x * 8 + warp;

        float2 h = reinterpret_cast<const float2*>(hidden + (size_t)row * MDIM)[lane];
        float wi0 = W[RDIM + lane * 2];
        float wi1 = W[RDIM + lane * 2 + 1];
        float wj0 = W[RDIM + MDIM + lane * 2];
        float wj1 = W[RDIM + MDIM + lane * 2 + 1];

        float si = h.x * wi0 + h.y * wi1;
        float sj = h.x * wj0 + h.y * wj1;
        #pragma unroll
        for (int off = 16; off >= 1; off >>= 1) {
            si += __shfl_xor_sync(0xFFFFFFFFu, si, off);
            sj += __shfl_xor_sync(0xFFFFFFFFu, sj, off);
        }
        if (lane == 0) {
            g_hi[row] = si;
            g_hj[row] = sj;
        }
        __threadfence();
        __syncthreads();
        if (tid == 0) atomicAdd(&g_pre, 1);
        return;
    }

    // ================= role 2: stream a quarter row =================
    float* part = pool;

    const int half = (lane >> 4);
    const int lh   = lane & 15;          // lane within half-warp
    const int hwid = warp * 2 + half;    // 0..15 half-warp id

    const int sid = blockIdx.x - NPRE;
    const int i   = sid >> 2;
    const int q   = sid & 3;
    const int j0  = q * QJ;

    {
        const float4 wv = __ldg(&reinterpret_cast<const float4*>(W)[lh]);
        const float4* p = reinterpret_cast<const float4*>(rela + (size_t)i * (P * RDIM))
                        + (size_t)(j0 + hwid) * 16 + lh;
        float4 buf[PF];
        #pragma unroll
        for (int qq = 0; qq < PF; qq++) buf[qq] = __ldcs(p + qq * 256);
        p += PF * 256;

        #pragma unroll
        for (int kk = 0; kk < (QJ / 16) / PF; kk++) {
            #pragma unroll
            for (int qq = 0; qq < PF; qq++) {
                float4 v = buf[qq];
                if (kk < (QJ / 16) / PF - 1) buf[qq] = __ldcs(p + qq * 256);
                float s = fmaf(v.x, wv.x, fmaf(v.y, wv.y, fmaf(v.z, wv.z, v.w * wv.w)));
                s += __shfl_xor_sync(0xFFFFFFFFu, s, 8);     // 16 -> 8
                s += __shfl_xor_sync(0xFFFFFFFFu, s, 4);     // 8 -> 4 partials
                const int jl = (kk * PF + qq) * 16 + hwid;
                if (lh < 4) part[jl * 5 + lh] = s;           // conflict-free (pad 5)
            }
            p += PF * 256;
        }
    }
    __syncthreads();

    // write RAW dot: thread tid <-> local j = tid
    {
        const float* pj = &part[tid * 5];          // stride 5: conflict-free
        float s = (pj[0] + pj[1]) + (pj[2] + pj[3]);
        g_dots[(size_t)i * P + j0 + tid] = s;      // coalesced 1 KB
    }

    // quarter done: 4th-quarter block becomes the row finisher
    __threadfence();
    __syncthreads();
    if (tid == 0) s_old = atomicAdd(&g_rowcnt[i], 1);
    __syncthreads();
    if (s_old != 3) return;

    // ================= finisher: softmax (regs) + GEMV (smem) =================
    if (tid == 0) {
        while (*(volatile int*)&g_pre < NPRE) __nanosleep(64);
    }
    __syncthreads();
    __threadfence();

    float4 v  = reinterpret_cast<const float4*>(g_dots + (size_t)i * P)[tid];
    int4  n4  = reinterpret_cast<const int4*>(nei + (size_t)i * P)[tid];
    float4 hj = reinterpret_cast<const float4*>(g_hj)[tid];
    const float hb = g_hi[i] + bptr[0];

    v.x = (n4.x > 0) ? (v.x + hj.x + hb) : 0.0f;  if (v.x == 0.0f) v.x = -1e-6f;
    v.y = (n4.y > 0) ? (v.y + hj.y + hb) : 0.0f;  if (v.y == 0.0f) v.y = -1e-6f;
    v.z = (n4.z > 0) ? (v.z + hj.z + hb) : 0.0f;  if (v.z == 0.0f) v.z = -1e-6f;
    v.w = (n4.w > 0) ? (v.w + hj.w + hb) : 0.0f;  if (v.w == 0.0f) v.w = -1e-6f;

    float mx = fmaxf(fmaxf(v.x, v.y), fmaxf(v.z, v.w));
    #pragma unroll
    for (int off = 16; off >= 1; off >>= 1)
        mx = fmaxf(mx, __shfl_xor_sync(0xFFFFFFFFu, mx, off));
    if (lane == 0) red[warp] = mx;
    __syncthreads();
    {
        float m = red[0];
        #pragma unroll
        for (int w = 1; w < 8; w++) m = fmaxf(m, red[w]);
        mx = m;
    }
    __syncthreads();

    float4 e;
    e.x = __expf(v.x - mx);
    e.y = __expf(v.y - mx);
    e.z = __expf(v.z - mx);
    e.w = __expf(v.w - mx);
    float sum = (e.x + e.y) + (e.z + e.w);
    #pragma unroll
    for (int off = 16; off >= 1; off >>= 1)
        sum += __shfl_xor_sync(0xFFFFFFFFu, sum, off);
    if (lane == 0) red[warp] = sum;
    __syncthreads();
    float inv;
    {
        float s = 0.0f;
        #pragma unroll
        for (int w = 0; w < 8; w++) s += red[w];
        inv = 1.0f / s;
    }

    // stage final attn row in SMEM (aliases part; safe after syncthreads)
    float* sat = pool;
    {
        float4 a;
        a.x = (n4.x > 0) ? e.x * inv : 0.0f;
        a.y = (n4.y > 0) ? e.y * inv : 0.0f;
        a.z = (n4.z > 0) ? e.z * inv : 0.0f;
        a.w = (n4.w > 0) ? e.w * inv : 0.0f;
        reinterpret_cast<float4*>(sat)[tid] = a;
    }
    __syncthreads();

    // GEMV: out[i, d] = sum_j attn[j] * hidden[j, d]
    // thread = (d-pair d2 = tid&31, j-group jg = warp: 128 consecutive j)
    {
        float* partb = pool + 1024;              // [8][64]
        const int d2 = tid & 31;
        const int jg = warp;                     // 0..7
        const float2* hidden2 = reinterpret_cast<const float2*>(hidden);

        float2 acc0 = make_float2(0.0f, 0.0f);
        float2 acc1 = make_float2(0.0f, 0.0f);

        #pragma unroll 2
        for (int jj = 0; jj < 128; jj += 4) {
            const int j = jg * 128 + jj;
            float4 a4 = *reinterpret_cast<const float4*>(sat + j);   // LDS broadcast
            float2 h0 = hidden2[(size_t)(j + 0) * 32 + d2];
            float2 h1 = hidden2[(size_t)(j + 1) * 32 + d2];
            float2 h2 = hidden2[(size_t)(j + 2) * 32 + d2];
            float2 h3 = hidden2[(size_t)(j + 3) * 32 + d2];
            acc0.x = fmaf(a4.x, h0.x, acc0.x); acc0.y = fmaf(a4.x, h0.y, acc0.y);
            acc1.x = fmaf(a4.y, h1.x, acc1.x); acc1.y = fmaf(a4.y, h1.y, acc1.y);
            acc0.x = fmaf(a4.z, h2.x, acc0.x); acc0.y = fmaf(a4.z, h2.y, acc0.y);
            acc1.x = fmaf(a4.w, h3.x, acc1.x); acc1.y = fmaf(a4.w, h3.y, acc1.y);
        }
        acc0.x += acc1.x;
        acc0.y += acc1.y;
        reinterpret_cast<float2*>(partb + jg * MDIM)[d2] = acc0;
    }
    __syncthreads();

    // reduce 8 jg-partials -> 64 outputs, plain stores (this block owns row i)
    if (tid < MDIM) {
        const float* pb = pool + 1024;
        float s = ((pb[0 * MDIM + tid] + pb[1 * MDIM + tid])
                +  (pb[2 * MDIM + tid] + pb[3 * MDIM + tid]))
                + ((pb[4 * MDIM + tid] + pb[5 * MDIM + tid])
                +  (pb[6 * MDIM + tid] + pb[7 * MDIM + tid]));
        out[(size_t)i * MDIM + tid] = s;
    }

    // replay-safe counter reset: this block owns row i; last finisher resets g_pre
    __syncthreads();
    if (tid == 0) {
        g_rowcnt[i] = 0;
        __threadfence();
        int old = atomicAdd(&g_fin, 1);
        if (old == P - 1) {       // all finishers done: nobody reads g_pre anymore
            g_pre = 0;
            g_fin = 0;
            __threadfence();
        }
    }
}

// ---------------------------------------------------------------------------
// Inputs (metadata order): 0 hidden_state f32[1024,64], 1 rela_state f32[1024,1024,64],
// 2 corr_index f32 (UNUSED), 3 nei_index i32[1024,1024], 4 W f32[192], 5 b f32[1].
// Output: f32[1024,64].
// ---------------------------------------------------------------------------
extern "C" void kernel_launch(void* const* d_in, const int* in_sizes, int n_in,
                              void* d_out, int out_size)
{
    const float* hidden = (const float*)d_in[0];
    const float* rela   = (const float*)d_in[1];
    const int*   nei    = (const int*)  d_in[3];
    const float* W      = (const float*)d_in[4];
    const float* b      = (const float*)d_in[5];
    float*       out    = (float*)d_out;

    fused_kernel<<<NPRE + NSTREAM, NTHR>>>(rela, hidden, nei, W, b, out);
}